// round 12
// baseline (speedup 1.0000x reference)
#include <cuda_runtime.h>
#include <math_constants.h>
#include <cstdint>

#define NROWS 2048
#define DIN   256
#define DPROJ 256   // Q[0:64) K[64:128) V[128:192) R[192:256)
#define DK    64
#define DR    64
#define DV    64

#define G_ROWS     8            // rows per CTA (one warp per row)
#define TILE_KEYS  32           // keys per smem K/V tile
#define HALF_KEYS  1024         // keys per CTA (row split in 2)
#define NT         (HALF_KEYS / TILE_KEYS)   // 32 tiles
#define NCTA_X     (NROWS / G_ROWS)          // 256
// dynamic smem: Ks[2][32][64] + Vs[2][32][64] + cm[32] + cl[32] + ca[8][4][64]
#define SMEM_FLOATS (2*TILE_KEYS*DK + 2*TILE_KEYS*DV + 32 + 32 + G_ROWS*4*DV)
#define SMEM_BYTES  (SMEM_FLOATS * 4)

// proj kernel smem: As[256][68] + Bs[256][68] (k-major, 64 rows used each)
#define PPAD 68
#define PROJ_SMEM_BYTES (2 * DIN * PPAD * 4)   // 139264

// Scratch
__device__ float g_proj[NROWS * DPROJ];          // projection (2 MB)
__device__ float g_ml[2][NROWS][2];              // per-half (M, L)
__device__ float g_pa[2][NROWS][DV];             // per-half unnormalized acc
__device__ int   g_cnt[NCTA_X];                  // arrival counters (reset by finisher)

__device__ __forceinline__ uint32_t smem_u32(const void* p) {
    return (uint32_t)__cvta_generic_to_shared(p);
}
__device__ __forceinline__ void cp16(uint32_t dst, const void* src) {
    asm volatile("cp.async.cg.shared.global [%0], [%1], 16;"
                 :: "r"(dst), "l"(src) : "memory");
}
// 256-bit single-use stream load with direct L2 evict-first (v8.b32 form).
__device__ __forceinline__ void ldg_v8(const float* p, float4& a, float4& b) {
    unsigned r0, r1, r2, r3, r4, r5, r6, r7;
    asm volatile(
        "ld.global.nc.L2::evict_first.v8.b32 {%0,%1,%2,%3,%4,%5,%6,%7}, [%8];"
        : "=r"(r0), "=r"(r1), "=r"(r2), "=r"(r3),
          "=r"(r4), "=r"(r5), "=r"(r6), "=r"(r7)
        : "l"(p));
    a.x = __uint_as_float(r0); a.y = __uint_as_float(r1);
    a.z = __uint_as_float(r2); a.w = __uint_as_float(r3);
    b.x = __uint_as_float(r4); b.y = __uint_as_float(r5);
    b.z = __uint_as_float(r6); b.w = __uint_as_float(r7);
}
__device__ __forceinline__ float dot4(const float4 a, const float4 b, float init) {
    float t = fmaf(a.x, b.x, init);
    t = fmaf(a.y, b.y, t);
    t = fmaf(a.z, b.z, t);
    return fmaf(a.w, b.w, t);
}

// ---------------------------------------------------------------------------
// Kernel 1: proj = H @ W^T.  (unchanged from R10 — at its shape floor)
// ---------------------------------------------------------------------------
__global__ __launch_bounds__(256, 1) void proj_gemm_kernel(
    const float* __restrict__ H, const float* __restrict__ W)
{
    extern __shared__ float psm[];
    float* As = psm;                   // [DIN][PPAD] rows 0..63 used
    float* Bs = psm + DIN * PPAD;      // [DIN][PPAD] rows 0..63 used

    const int tid = threadIdx.x;
    const int bm  = blockIdx.y * 64;
    const int bn  = blockIdx.x * 64;

    {
        const int row = tid >> 2;           // 0..63
        const int c   = (tid & 3) * 4;      // k sub-offset
#pragma unroll
        for (int kc = 0; kc < DIN; kc += 16) {
            float4 a4 = *(const float4*)&H[(size_t)(bm + row) * DIN + kc + c];
            As[(kc + c + 0) * PPAD + row] = a4.x;
            As[(kc + c + 1) * PPAD + row] = a4.y;
            As[(kc + c + 2) * PPAD + row] = a4.z;
            As[(kc + c + 3) * PPAD + row] = a4.w;
            float4 b4 = *(const float4*)&W[(size_t)(bn + row) * DIN + kc + c];
            Bs[(kc + c + 0) * PPAD + row] = b4.x;
            Bs[(kc + c + 1) * PPAD + row] = b4.y;
            Bs[(kc + c + 2) * PPAD + row] = b4.z;
            Bs[(kc + c + 3) * PPAD + row] = b4.w;
        }
    }
    __syncthreads();

    const int tx = tid & 15;
    const int ty = tid >> 4;

    float acc[4][4];
#pragma unroll
    for (int a = 0; a < 4; a++)
#pragma unroll
        for (int b = 0; b < 4; b++) acc[a][b] = 0.f;

#pragma unroll 4
    for (int k = 0; k < DIN; k++) {
        const float4 af = *(const float4*)&As[k * PPAD + ty * 4];
        const float4 bf = *(const float4*)&Bs[k * PPAD + tx * 4];
        acc[0][0] = fmaf(af.x, bf.x, acc[0][0]);
        acc[0][1] = fmaf(af.x, bf.y, acc[0][1]);
        acc[0][2] = fmaf(af.x, bf.z, acc[0][2]);
        acc[0][3] = fmaf(af.x, bf.w, acc[0][3]);
        acc[1][0] = fmaf(af.y, bf.x, acc[1][0]);
        acc[1][1] = fmaf(af.y, bf.y, acc[1][1]);
        acc[1][2] = fmaf(af.y, bf.z, acc[1][2]);
        acc[1][3] = fmaf(af.y, bf.w, acc[1][3]);
        acc[2][0] = fmaf(af.z, bf.x, acc[2][0]);
        acc[2][1] = fmaf(af.z, bf.y, acc[2][1]);
        acc[2][2] = fmaf(af.z, bf.z, acc[2][2]);
        acc[2][3] = fmaf(af.z, bf.w, acc[2][3]);
        acc[3][0] = fmaf(af.w, bf.x, acc[3][0]);
        acc[3][1] = fmaf(af.w, bf.y, acc[3][1]);
        acc[3][2] = fmaf(af.w, bf.z, acc[3][2]);
        acc[3][3] = fmaf(af.w, bf.w, acc[3][3]);
    }

#pragma unroll
    for (int a = 0; a < 4; a++)
        *(float4*)&g_proj[(size_t)(bm + ty * 4 + a) * DPROJ + bn + tx * 4] =
            make_float4(acc[a][0], acc[a][1], acc[a][2], acc[a][3]);
}

// ---------------------------------------------------------------------------
// Kernel 2: fused partial attention + in-kernel final combine.
// Grid (256, 2): blockIdx.x -> 8-row group, blockIdx.y = key half.
// Warp w owns row w. Warp split into 4 groups of 8 lanes (g = lane>>3);
// group g handles keys j == g (mod 4) with its own online-softmax state.
//   D·R : lane owns contiguous dims 8le..8le+7  -> one LDG.256 (v8,
//         evict-first) per key — half the LDG issue of the float4 version.
//   K·Q and V: lane owns split chunks {4le..4le+3} u {32+4le..+3} ->
//         conflict-free LDS.128 pairs from the same K/V smem tiles.
//   (Lane->dim maps may differ between the two partial dots: the 3-level
//    shfl-xor sum over the 8-lane group adds everything.)
// After the key loop: 4-way in-CTA combine per row -> per-half partials in
// global scratch; the SECOND CTA of each (row-group) pair (atomic counter)
// merges the two halves and writes out. No separate combine kernel.
// ---------------------------------------------------------------------------
__global__ void __launch_bounds__(256, 3) attn_partial_kernel(
    const float* __restrict__ D, float* __restrict__ out)
{
    extern __shared__ float smem[];
    float* Ks = smem;                       // [2][TILE_KEYS][DK]
    float* Vs = Ks + 2 * TILE_KEYS * DK;    // [2][TILE_KEYS][DV]
    float* cm = Vs + 2 * TILE_KEYS * DV;    // [G_ROWS][4]
    float* cl = cm + 32;                    // [G_ROWS][4]
    float* ca = cl + 32;                    // [G_ROWS][4][DV]
    __shared__ int s_last;

    const int tid  = threadIdx.x;
    const int warp = tid >> 5;           // = row within CTA
    const int lane = tid & 31;
    const int g    = lane >> 3;          // group in warp (0..3)
    const int le   = lane & 7;           // lane in group
    const int q    = blockIdx.y;         // key half
    const int i    = blockIdx.x * G_ROWS + warp;
    const int jq   = q * HALF_KEYS;

    const float scale = 0.08838834764831845f;  // 1/sqrt(128)
    // K.Q map: dims {4le..4le+3} and {32+4le..32+4le+3}
    float4 qa = *(const float4*)&g_proj[(size_t)i * DPROJ + 4 * le];
    float4 qb = *(const float4*)&g_proj[(size_t)i * DPROJ + 32 + 4 * le];
    // D.R map: dims {8le..8le+7}
    float4 ra = *(const float4*)&g_proj[(size_t)i * DPROJ + 192 + 8 * le];
    float4 rb = *(const float4*)&g_proj[(size_t)i * DPROJ + 192 + 8 * le + 4];
    qa.x *= scale; qa.y *= scale; qa.z *= scale; qa.w *= scale;
    qb.x *= scale; qb.y *= scale; qb.z *= scale; qb.w *= scale;
    ra.x *= scale; ra.y *= scale; ra.z *= scale; ra.w *= scale;
    rb.x *= scale; rb.y *= scale; rb.z *= scale; rb.w *= scale;

    const float* Drow = D + (size_t)i * NROWS * DR;

    // ---- prefetch tile 0 (K+V: 32 keys x 256B each = 16 KB) ----
    {
#pragma unroll
        for (int r = 0; r < 2; r++) {
            const int c   = tid + r * 256;      // 0..511
            const int key = c >> 4;
            const int off = c & 15;             // 16B units
            const float* src = &g_proj[(size_t)(jq + key) * DPROJ + off * 4];
            cp16(smem_u32(&Ks[key * DK + off * 4]), src + DK);
            cp16(smem_u32(&Vs[key * DV + off * 4]), src + 2 * DK);
        }
        asm volatile("cp.async.commit_group;" ::: "memory");
    }

    float  m = -CUDART_INF_F;
    float  l = 0.f;
    float4 acca = make_float4(0.f, 0.f, 0.f, 0.f);
    float4 accb = make_float4(0.f, 0.f, 0.f, 0.f);

#pragma unroll 1
    for (int t = 0; t < NT; t++) {
        const int st = t & 1;
        if (t + 1 < NT) {
            const int jt = jq + (t + 1) * TILE_KEYS;
            const int sn = (t + 1) & 1;
#pragma unroll
            for (int r = 0; r < 2; r++) {
                const int c   = tid + r * 256;
                const int key = c >> 4;
                const int off = c & 15;
                const float* src = &g_proj[(size_t)(jt + key) * DPROJ + off * 4];
                cp16(smem_u32(&Ks[sn * TILE_KEYS * DK + key * DK + off * 4]), src + DK);
                cp16(smem_u32(&Vs[sn * TILE_KEYS * DV + key * DV + off * 4]), src + 2 * DK);
            }
            asm volatile("cp.async.commit_group;" ::: "memory");
            asm volatile("cp.async.wait_group 1;" ::: "memory");
        } else {
            asm volatile("cp.async.wait_group 0;" ::: "memory");
        }
        __syncthreads();

        const float* Kt = Ks + st * TILE_KEYS * DK;
        const float* Vt = Vs + st * TILE_KEYS * DV;
        const int jt0 = jq + t * TILE_KEYS;

#pragma unroll
        for (int s = 0; s < 4; s++) {
            const int kk0 = s * 8 + g;          // in-tile keys for this group
            const int kk1 = kk0 + 4;

            // ---- D: two 256-bit evict-first stream loads ----
            float4 d0a, d0b, d1a, d1b;
            ldg_v8(&Drow[(size_t)(jt0 + kk0) * DR + 8 * le], d0a, d0b);
            ldg_v8(&Drow[(size_t)(jt0 + kk1) * DR + 8 * le], d1a, d1b);

            // ---- K: conflict-free split-chunk LDS.128 ----
            const float4 k0a = *(const float4*)&Kt[kk0 * DK + 4 * le];
            const float4 k0b = *(const float4*)&Kt[kk0 * DK + 32 + 4 * le];
            const float4 k1a = *(const float4*)&Kt[kk1 * DK + 4 * le];
            const float4 k1b = *(const float4*)&Kt[kk1 * DK + 32 + 4 * le];

            float sc0 = dot4(d0a, ra, 0.f);
            sc0 = dot4(d0b, rb, sc0);
            sc0 = dot4(k0a, qa, sc0);
            sc0 = dot4(k0b, qb, sc0);
            float sc1 = dot4(d1a, ra, 0.f);
            sc1 = dot4(d1b, rb, sc1);
            sc1 = dot4(k1a, qa, sc1);
            sc1 = dot4(k1b, qb, sc1);

            // 3-level butterfly within the 8-lane group
#pragma unroll
            for (int o = 1; o < 8; o <<= 1) {
                sc0 += __shfl_xor_sync(0xffffffffu, sc0, o);
                sc1 += __shfl_xor_sync(0xffffffffu, sc1, o);
            }

            const float mnew = fmaxf(m, fmaxf(sc0, sc1));
            const float c  = __expf(m - mnew);
            const float w0 = __expf(sc0 - mnew);
            const float w1 = __expf(sc1 - mnew);
            l = fmaf(l, c, w0 + w1);

            const float4 v0a = *(const float4*)&Vt[kk0 * DV + 4 * le];
            const float4 v0b = *(const float4*)&Vt[kk0 * DV + 32 + 4 * le];
            const float4 v1a = *(const float4*)&Vt[kk1 * DV + 4 * le];
            const float4 v1b = *(const float4*)&Vt[kk1 * DV + 32 + 4 * le];

            acca.x = fmaf(w1, v1a.x, fmaf(w0, v0a.x, acca.x * c));
            acca.y = fmaf(w1, v1a.y, fmaf(w0, v0a.y, acca.y * c));
            acca.z = fmaf(w1, v1a.z, fmaf(w0, v0a.z, acca.z * c));
            acca.w = fmaf(w1, v1a.w, fmaf(w0, v0a.w, acca.w * c));
            accb.x = fmaf(w1, v1b.x, fmaf(w0, v0b.x, accb.x * c));
            accb.y = fmaf(w1, v1b.y, fmaf(w0, v0b.y, accb.y * c));
            accb.z = fmaf(w1, v1b.z, fmaf(w0, v0b.z, accb.z * c));
            accb.w = fmaf(w1, v1b.w, fmaf(w0, v0b.w, accb.w * c));
            m = mnew;
        }
        __syncthreads();   // tile consumed
    }

    // ---- in-CTA combine of the 4 group-partials per row ----
    const int p = warp * 4 + g;
    if (le == 0) { cm[p] = m; cl[p] = l; }
    *(float4*)&ca[p * DV + 4 * le]      = acca;   // dims 4le..4le+3
    *(float4*)&ca[p * DV + 32 + 4 * le] = accb;   // dims 32+4le..+3
    __syncthreads();

    {
        const int row = tid >> 5;           // 0..7
        const int dd  = (tid & 31) * 2;     // 2 dims per thread
        const int ig  = blockIdx.x * G_ROWS + row;
        float M = cm[row * 4 + 0];
#pragma unroll
        for (int w = 1; w < 4; w++) M = fmaxf(M, cm[row * 4 + w]);
        float L = 0.f, o0 = 0.f, o1 = 0.f;
#pragma unroll
        for (int w = 0; w < 4; w++) {
            const float e = __expf(cm[row * 4 + w] - M);
            L  = fmaf(cl[row * 4 + w], e, L);
            o0 = fmaf(ca[(row * 4 + w) * DV + dd + 0], e, o0);
            o1 = fmaf(ca[(row * 4 + w) * DV + dd + 1], e, o1);
        }
        g_pa[q][ig][dd + 0] = o0;
        g_pa[q][ig][dd + 1] = o1;
        if (dd == 0) { g_ml[q][ig][0] = M; g_ml[q][ig][1] = L; }
    }

    // ---- cross-half merge: second-arriving CTA of the pair finishes ----
    __threadfence();
    __syncthreads();
    if (tid == 0)
        s_last = (atomicAdd(&g_cnt[blockIdx.x], 1) == 1);
    __syncthreads();

    if (s_last) {
        __threadfence();
        const int row = tid >> 5;
        const int dd  = (tid & 31) * 2;
        const int ig  = blockIdx.x * G_ROWS + row;
        const float m0 = g_ml[0][ig][0], l0 = g_ml[0][ig][1];
        const float m1 = g_ml[1][ig][0], l1 = g_ml[1][ig][1];
        const float M  = fmaxf(m0, m1);
        const float e0 = __expf(m0 - M);
        const float e1 = __expf(m1 - M);
        const float L  = e0 * l0 + e1 * l1;
        const float r0 = (e0 * g_pa[0][ig][dd + 0] + e1 * g_pa[1][ig][dd + 0]) / L;
        const float r1 = (e0 * g_pa[0][ig][dd + 1] + e1 * g_pa[1][ig][dd + 1]) / L;
        *(float2*)&out[(size_t)ig * DV + dd] = make_float2(r0, r1);
        if (tid == 0) g_cnt[blockIdx.x] = 0;   // reset for next graph replay
    }
}

// ---------------------------------------------------------------------------
extern "C" void kernel_launch(void* const* d_in, const int* in_sizes, int n_in,
                              void* d_out, int out_size)
{
    const float* H = (const float*)d_in[0];   // (2048, 256)
    const float* D = (const float*)d_in[1];   // (2048, 2048, 64)
    const float* W = (const float*)d_in[2];   // (256, 256)
    float* out = (float*)d_out;               // (2048, 64)

    static bool attr_set = false;
    if (!attr_set) {
        cudaFuncSetAttribute(attn_partial_kernel,
                             cudaFuncAttributeMaxDynamicSharedMemorySize, SMEM_BYTES);
        cudaFuncSetAttribute(proj_gemm_kernel,
                             cudaFuncAttributeMaxDynamicSharedMemorySize, PROJ_SMEM_BYTES);
        attr_set = true;
    }

    dim3 g1(DPROJ / 64, NROWS / 64);          // (4, 32) = 128 blocks
    proj_gemm_kernel<<<g1, 256, PROJ_SMEM_BYTES>>>(H, W);
    attn_partial_kernel<<<dim3(NCTA_X, 2), 256, SMEM_BYTES>>>(D, out);
}

// round 14
// speedup vs baseline: 1.2659x; 1.2659x over previous
#include <cuda_runtime.h>
#include <math_constants.h>
#include <cstdint>

#define NROWS 2048
#define DIN   256
#define DPROJ 256   // Q[0:64) K[64:128) V[128:192) R[192:256)
#define DK    64
#define DR    64
#define DV    64

#define G_ROWS     8            // rows per CTA (one warp per row)
#define TILE_KEYS  32           // keys per smem K/V tile
#define HALF_KEYS  1024         // keys per CTA (row split in 2)
#define NT         (HALF_KEYS / TILE_KEYS)   // 32 tiles
#define NCTA_X     (NROWS / G_ROWS)          // 256
// dynamic smem: Ks[2][32][64] + Vs[2][32][64] + cm[16] + cl[16] + ca[8][2][64]
#define SMEM_FLOATS (2*TILE_KEYS*DK + 2*TILE_KEYS*DV + 16 + 16 + G_ROWS*2*DV)
#define SMEM_BYTES  (SMEM_FLOATS * 4)

// proj kernel smem: As[256][68] + Bs[256][68] (k-major, 64 rows used each)
#define PPAD 68
#define PROJ_SMEM_BYTES (2 * DIN * PPAD * 4)   // 139264

// Scratch
__device__ float g_proj[NROWS * DPROJ];          // projection (2 MB)
__device__ float g_ml[2][NROWS][2];              // per-half (M, L)
__device__ float g_pa[2][NROWS][DV];             // per-half unnormalized acc
__device__ int   g_cnt[NCTA_X];                  // arrival counters (reset by finisher)

__device__ __forceinline__ uint32_t smem_u32(const void* p) {
    return (uint32_t)__cvta_generic_to_shared(p);
}
__device__ __forceinline__ void cp16(uint32_t dst, const void* src) {
    asm volatile("cp.async.cg.shared.global [%0], [%1], 16;"
                 :: "r"(dst), "l"(src) : "memory");
}
__device__ __forceinline__ uint64_t mk_evict_first_policy() {
    uint64_t pol;
    asm("createpolicy.fractional.L2::evict_first.b64 %0, 1.0;" : "=l"(pol));
    return pol;
}
__device__ __forceinline__ float4 ldg_stream(const float* p, uint64_t pol) {
    float4 v;
    asm volatile("ld.global.nc.L2::cache_hint.v4.f32 {%0,%1,%2,%3}, [%4], %5;"
                 : "=f"(v.x), "=f"(v.y), "=f"(v.z), "=f"(v.w)
                 : "l"(p), "l"(pol));
    return v;
}

// ---------------------------------------------------------------------------
// Kernel 1: proj = H @ W^T.  (R10 version — at its shape floor, 16 us)
// ---------------------------------------------------------------------------
__global__ __launch_bounds__(256, 1) void proj_gemm_kernel(
    const float* __restrict__ H, const float* __restrict__ W)
{
    extern __shared__ float psm[];
    float* As = psm;                   // [DIN][PPAD] rows 0..63 used
    float* Bs = psm + DIN * PPAD;      // [DIN][PPAD] rows 0..63 used

    const int tid = threadIdx.x;
    const int bm  = blockIdx.y * 64;
    const int bn  = blockIdx.x * 64;

    {
        const int row = tid >> 2;           // 0..63
        const int c   = (tid & 3) * 4;      // k sub-offset
#pragma unroll
        for (int kc = 0; kc < DIN; kc += 16) {
            float4 a4 = *(const float4*)&H[(size_t)(bm + row) * DIN + kc + c];
            As[(kc + c + 0) * PPAD + row] = a4.x;
            As[(kc + c + 1) * PPAD + row] = a4.y;
            As[(kc + c + 2) * PPAD + row] = a4.z;
            As[(kc + c + 3) * PPAD + row] = a4.w;
            float4 b4 = *(const float4*)&W[(size_t)(bn + row) * DIN + kc + c];
            Bs[(kc + c + 0) * PPAD + row] = b4.x;
            Bs[(kc + c + 1) * PPAD + row] = b4.y;
            Bs[(kc + c + 2) * PPAD + row] = b4.z;
            Bs[(kc + c + 3) * PPAD + row] = b4.w;
        }
    }
    __syncthreads();

    const int tx = tid & 15;
    const int ty = tid >> 4;

    float acc[4][4];
#pragma unroll
    for (int a = 0; a < 4; a++)
#pragma unroll
        for (int b = 0; b < 4; b++) acc[a][b] = 0.f;

#pragma unroll 4
    for (int k = 0; k < DIN; k++) {
        const float4 af = *(const float4*)&As[k * PPAD + ty * 4];
        const float4 bf = *(const float4*)&Bs[k * PPAD + tx * 4];
        acc[0][0] = fmaf(af.x, bf.x, acc[0][0]);
        acc[0][1] = fmaf(af.x, bf.y, acc[0][1]);
        acc[0][2] = fmaf(af.x, bf.z, acc[0][2]);
        acc[0][3] = fmaf(af.x, bf.w, acc[0][3]);
        acc[1][0] = fmaf(af.y, bf.x, acc[1][0]);
        acc[1][1] = fmaf(af.y, bf.y, acc[1][1]);
        acc[1][2] = fmaf(af.y, bf.z, acc[1][2]);
        acc[1][3] = fmaf(af.y, bf.w, acc[1][3]);
        acc[2][0] = fmaf(af.z, bf.x, acc[2][0]);
        acc[2][1] = fmaf(af.z, bf.y, acc[2][1]);
        acc[2][2] = fmaf(af.z, bf.z, acc[2][2]);
        acc[2][3] = fmaf(af.z, bf.w, acc[2][3]);
        acc[3][0] = fmaf(af.w, bf.x, acc[3][0]);
        acc[3][1] = fmaf(af.w, bf.y, acc[3][1]);
        acc[3][2] = fmaf(af.w, bf.z, acc[3][2]);
        acc[3][3] = fmaf(af.w, bf.w, acc[3][3]);
    }

#pragma unroll
    for (int a = 0; a < 4; a++)
        *(float4*)&g_proj[(size_t)(bm + ty * 4 + a) * DPROJ + bn + tx * 4] =
            make_float4(acc[a][0], acc[a][1], acc[a][2], acc[a][3]);
}

// ---------------------------------------------------------------------------
// Kernel 2: partial fused attention (exact R10 inner loop) + fused final
// combine (second-arriving CTA of each row-group pair merges the two
// key-halves and writes out; no third kernel).
// Grid (256, 2): blockIdx.x -> 8-row group, blockIdx.y = key half.
// Warp w owns row w; 16-lane groups (h = lane>>4) own alternating keys,
// lane&15 owns 4 dims; K/V double-buffered smem tiles via cp.async;
// D streamed as 4 back-to-back float4 LDG (evict-first cache hint).
// ---------------------------------------------------------------------------
__global__ void __launch_bounds__(256, 4) attn_partial_kernel(
    const float* __restrict__ D, float* __restrict__ out)
{
    extern __shared__ float smem[];
    float* Ks = smem;                       // [2][TILE_KEYS][DK]
    float* Vs = Ks + 2 * TILE_KEYS * DK;    // [2][TILE_KEYS][DV]
    float* cm = Vs + 2 * TILE_KEYS * DV;    // [G_ROWS][2]
    float* cl = cm + 16;                    // [G_ROWS][2]
    float* ca = cl + 16;                    // [G_ROWS][2][DV]
    __shared__ int s_last;

    const int tid  = threadIdx.x;
    const int warp = tid >> 5;           // = row within CTA
    const int lane = tid & 31;
    const int h    = lane >> 4;          // group in warp
    const int lx   = lane & 15;          // lane in group -> dims 4*lx..+4
    const int q    = blockIdx.y;         // key half
    const int i    = blockIdx.x * G_ROWS + warp;
    const int jq   = q * HALF_KEYS;

    const uint64_t pol = mk_evict_first_policy();

    const float scale = 0.08838834764831845f;  // 1/sqrt(128)
    float4 q4 = *(const float4*)&g_proj[(size_t)i * DPROJ + 4 * lx];
    float4 r4 = *(const float4*)&g_proj[(size_t)i * DPROJ + 192 + 4 * lx];
    q4.x *= scale; q4.y *= scale; q4.z *= scale; q4.w *= scale;
    r4.x *= scale; r4.y *= scale; r4.z *= scale; r4.w *= scale;

    const float* Drow = D + (size_t)i * NROWS * DR;

    // ---- prefetch tile 0 (K+V: 32 keys x 256B each = 16 KB) ----
    {
#pragma unroll
        for (int r = 0; r < 2; r++) {
            const int c   = tid + r * 256;      // 0..511
            const int key = c >> 4;
            const int off = c & 15;             // 16B units
            const float* src = &g_proj[(size_t)(jq + key) * DPROJ + off * 4];
            cp16(smem_u32(&Ks[key * DK + off * 4]), src + DK);
            cp16(smem_u32(&Vs[key * DV + off * 4]), src + 2 * DK);
        }
        asm volatile("cp.async.commit_group;" ::: "memory");
    }

    float  m = -CUDART_INF_F;
    float  l = 0.f;
    float4 acc = make_float4(0.f, 0.f, 0.f, 0.f);

#pragma unroll 1
    for (int t = 0; t < NT; t++) {
        const int st = t & 1;
        if (t + 1 < NT) {
            const int jt = jq + (t + 1) * TILE_KEYS;
            const int sn = (t + 1) & 1;
#pragma unroll
            for (int r = 0; r < 2; r++) {
                const int c   = tid + r * 256;
                const int key = c >> 4;
                const int off = c & 15;
                const float* src = &g_proj[(size_t)(jt + key) * DPROJ + off * 4];
                cp16(smem_u32(&Ks[sn * TILE_KEYS * DK + key * DK + off * 4]), src + DK);
                cp16(smem_u32(&Vs[sn * TILE_KEYS * DV + key * DV + off * 4]), src + 2 * DK);
            }
            asm volatile("cp.async.commit_group;" ::: "memory");
            asm volatile("cp.async.wait_group 1;" ::: "memory");
        } else {
            asm volatile("cp.async.wait_group 0;" ::: "memory");
        }
        __syncthreads();

        const float* Kt = Ks + st * TILE_KEYS * DK;
        const float* Vt = Vs + st * TILE_KEYS * DV;
        const int jt0 = jq + t * TILE_KEYS;

#pragma unroll
        for (int s = 0; s < 4; s++) {
            // ---- 8 keys per batch: 4 back-to-back 2KB-contiguous D loads ----
            float4 d4[4];
            float  sc[4];
#pragma unroll
            for (int u = 0; u < 4; u++) {
                const int kk = s * 8 + 2 * u + h;
                d4[u] = ldg_stream(&Drow[(size_t)(jt0 + kk) * DR + 4 * lx], pol);
            }
#pragma unroll
            for (int u = 0; u < 4; u++) {
                const int kk = s * 8 + 2 * u + h;
                const float4 k4 = *(const float4*)&Kt[kk * DK + 4 * lx];
                float t0 = d4[u].x * r4.x;
                t0 = fmaf(d4[u].y, r4.y, t0);
                t0 = fmaf(d4[u].z, r4.z, t0);
                t0 = fmaf(d4[u].w, r4.w, t0);
                t0 = fmaf(k4.x, q4.x, t0);
                t0 = fmaf(k4.y, q4.y, t0);
                t0 = fmaf(k4.z, q4.z, t0);
                t0 = fmaf(k4.w, q4.w, t0);
                sc[u] = t0;
            }
#pragma unroll
            for (int o = 1; o < 16; o <<= 1) {
#pragma unroll
                for (int u = 0; u < 4; u++)
                    sc[u] += __shfl_xor_sync(0xffffffffu, sc[u], o);
            }
            const float mnew = fmaxf(fmaxf(fmaxf(sc[0], sc[1]), fmaxf(sc[2], sc[3])), m);
            const float c = __expf(m - mnew);
            float w[4];
#pragma unroll
            for (int u = 0; u < 4; u++) w[u] = __expf(sc[u] - mnew);
            l = fmaf(l, c, (w[0] + w[1]) + (w[2] + w[3]));
            float ax = acc.x * c, ay = acc.y * c, az = acc.z * c, aw = acc.w * c;
#pragma unroll
            for (int u = 0; u < 4; u++) {
                const int kk = s * 8 + 2 * u + h;
                const float4 v4 = *(const float4*)&Vt[kk * DV + 4 * lx];
                ax = fmaf(w[u], v4.x, ax);
                ay = fmaf(w[u], v4.y, ay);
                az = fmaf(w[u], v4.z, az);
                aw = fmaf(w[u], v4.w, aw);
            }
            acc.x = ax; acc.y = ay; acc.z = az; acc.w = aw;
            m = mnew;
        }
        __syncthreads();   // tile consumed
    }

    // ---- combine the 2 group-partials per row ----
    if (lx == 0) { cm[warp * 2 + h] = m; cl[warp * 2 + h] = l; }
    *(float4*)&ca[(warp * 2 + h) * DV + 4 * lx] = acc;
    __syncthreads();

    {
        const int row = tid >> 5;           // 0..7
        const int dd  = (tid & 31) * 2;     // 2 dims per thread
        const int ig  = blockIdx.x * G_ROWS + row;
        const float m0 = cm[row * 2 + 0], m1 = cm[row * 2 + 1];
        const float M  = fmaxf(m0, m1);
        const float e0 = __expf(m0 - M);
        const float e1 = __expf(m1 - M);
        const float L  = e0 * cl[row * 2 + 0] + e1 * cl[row * 2 + 1];
        const float o0 = e0 * ca[(row * 2 + 0) * DV + dd + 0]
                       + e1 * ca[(row * 2 + 1) * DV + dd + 0];
        const float o1 = e0 * ca[(row * 2 + 0) * DV + dd + 1]
                       + e1 * ca[(row * 2 + 1) * DV + dd + 1];
        g_pa[q][ig][dd + 0] = o0;
        g_pa[q][ig][dd + 1] = o1;
        if (dd == 0) { g_ml[q][ig][0] = M; g_ml[q][ig][1] = L; }
    }

    // ---- cross-half merge: second-arriving CTA of the pair finishes ----
    __threadfence();
    __syncthreads();
    if (tid == 0)
        s_last = (atomicAdd(&g_cnt[blockIdx.x], 1) == 1);
    __syncthreads();

    if (s_last) {
        __threadfence();
        const int row = tid >> 5;
        const int dd  = (tid & 31) * 2;
        const int ig  = blockIdx.x * G_ROWS + row;
        const float m0 = g_ml[0][ig][0], l0 = g_ml[0][ig][1];
        const float m1 = g_ml[1][ig][0], l1 = g_ml[1][ig][1];
        const float M  = fmaxf(m0, m1);
        const float e0 = __expf(m0 - M);
        const float e1 = __expf(m1 - M);
        const float L  = e0 * l0 + e1 * l1;
        const float r0 = (e0 * g_pa[0][ig][dd + 0] + e1 * g_pa[1][ig][dd + 0]) / L;
        const float r1 = (e0 * g_pa[0][ig][dd + 1] + e1 * g_pa[1][ig][dd + 1]) / L;
        *(float2*)&out[(size_t)ig * DV + dd] = make_float2(r0, r1);
        if (tid == 0) g_cnt[blockIdx.x] = 0;   // reset for next graph replay
    }
}

// ---------------------------------------------------------------------------
extern "C" void kernel_launch(void* const* d_in, const int* in_sizes, int n_in,
                              void* d_out, int out_size)
{
    const float* H = (const float*)d_in[0];   // (2048, 256)
    const float* D = (const float*)d_in[1];   // (2048, 2048, 64)
    const float* W = (const float*)d_in[2];   // (256, 256)
    float* out = (float*)d_out;               // (2048, 64)

    static bool attr_set = false;
    if (!attr_set) {
        cudaFuncSetAttribute(attn_partial_kernel,
                             cudaFuncAttributeMaxDynamicSharedMemorySize, SMEM_BYTES);
        cudaFuncSetAttribute(proj_gemm_kernel,
                             cudaFuncAttributeMaxDynamicSharedMemorySize, PROJ_SMEM_BYTES);
        attr_set = true;
    }

    dim3 g1(DPROJ / 64, NROWS / 64);          // (4, 32) = 128 blocks
    proj_gemm_kernel<<<g1, 256, PROJ_SMEM_BYTES>>>(H, W);
    attn_partial_kernel<<<dim3(NCTA_X, 2), 256, SMEM_BYTES>>>(D, out);
}

// round 15
// speedup vs baseline: 1.2797x; 1.0109x over previous
#include <cuda_runtime.h>
#include <math_constants.h>
#include <cstdint>

#define NROWS 2048
#define DIN   256
#define DPROJ 256   // Q[0:64) K[64:128) V[128:192) R[192:256)
#define DK    64
#define DR    64
#define DV    64

#define G_ROWS     8            // rows per CTA (one warp per row)
#define TILE_KEYS  32           // keys per smem K/V tile
#define SPLITS     4            // key splits per row
#define KEYS_PER_CTA (NROWS / SPLITS)        // 512
#define NT         (KEYS_PER_CTA / TILE_KEYS) // 16 tiles
#define NCTA_X     (NROWS / G_ROWS)          // 256
// dynamic smem: Ks[2][32][64] + Vs[2][32][64] + cm[16] + cl[16] + ca[8][2][64]
#define SMEM_FLOATS (2*TILE_KEYS*DK + 2*TILE_KEYS*DV + 16 + 16 + G_ROWS*2*DV)
#define SMEM_BYTES  (SMEM_FLOATS * 4)

// proj kernel smem: As[256][68] + Bs[256][68] (k-major, 64 rows used each)
#define PPAD 68
#define PROJ_SMEM_BYTES (2 * DIN * PPAD * 4)   // 139264

// Scratch
__device__ float g_proj[NROWS * DPROJ];          // projection (2 MB)
__device__ float g_ml[SPLITS][NROWS][2];         // per-split (M, L)
__device__ float g_pa[SPLITS][NROWS][DV];        // per-split unnormalized acc

__device__ __forceinline__ uint32_t smem_u32(const void* p) {
    return (uint32_t)__cvta_generic_to_shared(p);
}
__device__ __forceinline__ void cp16(uint32_t dst, const void* src) {
    asm volatile("cp.async.cg.shared.global [%0], [%1], 16;"
                 :: "r"(dst), "l"(src) : "memory");
}
__device__ __forceinline__ uint64_t mk_evict_first_policy() {
    uint64_t pol;
    asm("createpolicy.fractional.L2::evict_first.b64 %0, 1.0;" : "=l"(pol));
    return pol;
}
__device__ __forceinline__ float4 ldg_stream(const float* p, uint64_t pol) {
    float4 v;
    asm volatile("ld.global.nc.L2::cache_hint.v4.f32 {%0,%1,%2,%3}, [%4], %5;"
                 : "=f"(v.x), "=f"(v.y), "=f"(v.z), "=f"(v.w)
                 : "l"(p), "l"(pol));
    return v;
}
// ---- packed f32x2 helpers (sm_103a FFMA2 path) ----
__device__ __forceinline__ void fma2(unsigned long long& d,
                                     unsigned long long a,
                                     unsigned long long b) {
    asm("fma.rn.f32x2 %0, %1, %2, %0;" : "+l"(d) : "l"(a), "l"(b));
}
__device__ __forceinline__ unsigned long long bcast2(float x) {
    unsigned long long r;
    asm("mov.b64 %0, {%1, %1};" : "=l"(r) : "f"(x));
    return r;
}
__device__ __forceinline__ float lo2(unsigned long long v) {
    return __uint_as_float((unsigned)(v & 0xffffffffu));
}
__device__ __forceinline__ float hi2(unsigned long long v) {
    return __uint_as_float((unsigned)(v >> 32));
}

// ---------------------------------------------------------------------------
// Kernel 1: proj = H @ W^T.  64x64 tile, 128 threads, 8x4 micro-tile with
// packed f32x2 FMA (halves FMA issue count). Full-K k-major staging, one
// barrier. Grid (4,32)=128 CTAs, 1 CTA/SM.
// ---------------------------------------------------------------------------
__global__ __launch_bounds__(128, 1) void proj_gemm_kernel(
    const float* __restrict__ H, const float* __restrict__ W)
{
    extern __shared__ float psm[];
    float* As = psm;                   // [DIN][PPAD] rows 0..63 used
    float* Bs = psm + DIN * PPAD;      // [DIN][PPAD] rows 0..63 used

    const int tid = threadIdx.x;
    const int bm  = blockIdx.y * 64;
    const int bn  = blockIdx.x * 64;

    // ---- stage H and W tiles (64 x 256 each), k-major ----
    {
        const int row = tid >> 1;           // 0..63
        const int cb  = (tid & 1) * 4;      // 0 or 4
#pragma unroll
        for (int kc = 0; kc < DIN; kc += 8) {
            float4 a4 = *(const float4*)&H[(size_t)(bm + row) * DIN + kc + cb];
            As[(kc + cb + 0) * PPAD + row] = a4.x;
            As[(kc + cb + 1) * PPAD + row] = a4.y;
            As[(kc + cb + 2) * PPAD + row] = a4.z;
            As[(kc + cb + 3) * PPAD + row] = a4.w;
            float4 b4 = *(const float4*)&W[(size_t)(bn + row) * DIN + kc + cb];
            Bs[(kc + cb + 0) * PPAD + row] = b4.x;
            Bs[(kc + cb + 1) * PPAD + row] = b4.y;
            Bs[(kc + cb + 2) * PPAD + row] = b4.z;
            Bs[(kc + cb + 3) * PPAD + row] = b4.w;
        }
    }
    __syncthreads();   // the only barrier

    const int tx = tid & 15;        // 4 output cols
    const int ty = tid >> 4;        // 8 output rows (4 row-pairs)

    unsigned long long acc2[4][4];
#pragma unroll
    for (int a = 0; a < 4; a++)
#pragma unroll
        for (int b = 0; b < 4; b++) acc2[a][b] = 0ull;

#pragma unroll 4
    for (int k = 0; k < DIN; k++) {
        // 8 a-values = 4 packed row-pairs (direct reinterpret of LDS.128)
        const ulonglong2 aA = *(const ulonglong2*)&As[k * PPAD + ty * 8];
        const ulonglong2 aB = *(const ulonglong2*)&As[k * PPAD + ty * 8 + 4];
        const float4 bf = *(const float4*)&Bs[k * PPAD + tx * 4];
        const unsigned long long bp0 = bcast2(bf.x);
        const unsigned long long bp1 = bcast2(bf.y);
        const unsigned long long bp2 = bcast2(bf.z);
        const unsigned long long bp3 = bcast2(bf.w);

        fma2(acc2[0][0], aA.x, bp0); fma2(acc2[0][1], aA.x, bp1);
        fma2(acc2[0][2], aA.x, bp2); fma2(acc2[0][3], aA.x, bp3);
        fma2(acc2[1][0], aA.y, bp0); fma2(acc2[1][1], aA.y, bp1);
        fma2(acc2[1][2], aA.y, bp2); fma2(acc2[1][3], aA.y, bp3);
        fma2(acc2[2][0], aB.x, bp0); fma2(acc2[2][1], aB.x, bp1);
        fma2(acc2[2][2], aB.x, bp2); fma2(acc2[2][3], aB.x, bp3);
        fma2(acc2[3][0], aB.y, bp0); fma2(acc2[3][1], aB.y, bp1);
        fma2(acc2[3][2], aB.y, bp2); fma2(acc2[3][3], aB.y, bp3);
    }

#pragma unroll
    for (int rp = 0; rp < 4; rp++) {
        const int row = bm + ty * 8 + rp * 2;
        *(float4*)&g_proj[(size_t)row * DPROJ + bn + tx * 4] =
            make_float4(lo2(acc2[rp][0]), lo2(acc2[rp][1]),
                        lo2(acc2[rp][2]), lo2(acc2[rp][3]));
        *(float4*)&g_proj[(size_t)(row + 1) * DPROJ + bn + tx * 4] =
            make_float4(hi2(acc2[rp][0]), hi2(acc2[rp][1]),
                        hi2(acc2[rp][2]), hi2(acc2[rp][3]));
    }
}

// ---------------------------------------------------------------------------
// Kernel 2: partial fused attention (exact R10 inner loop), 4-way key split.
// Grid (256, 4): blockIdx.x -> 8-row group, blockIdx.y = key quarter.
// Warp w owns row w; 16-lane groups (h = lane>>4) own alternating keys,
// lane&15 owns 4 dims; K/V double-buffered smem tiles via cp.async;
// D streamed as 4 back-to-back float4 LDG (evict-first cache hint).
// 1024 CTAs > 592 resident -> work-stealing erases wave quantization.
// ---------------------------------------------------------------------------
__global__ void __launch_bounds__(256, 4) attn_partial_kernel(
    const float* __restrict__ D)
{
    extern __shared__ float smem[];
    float* Ks = smem;                       // [2][TILE_KEYS][DK]
    float* Vs = Ks + 2 * TILE_KEYS * DK;    // [2][TILE_KEYS][DV]
    float* cm = Vs + 2 * TILE_KEYS * DV;    // [G_ROWS][2]
    float* cl = cm + 16;                    // [G_ROWS][2]
    float* ca = cl + 16;                    // [G_ROWS][2][DV]

    const int tid  = threadIdx.x;
    const int warp = tid >> 5;           // = row within CTA
    const int lane = tid & 31;
    const int h    = lane >> 4;          // group in warp
    const int lx   = lane & 15;          // lane in group -> dims 4*lx..+4
    const int q    = blockIdx.y;         // key quarter
    const int i    = blockIdx.x * G_ROWS + warp;
    const int jq   = q * KEYS_PER_CTA;

    const uint64_t pol = mk_evict_first_policy();

    const float scale = 0.08838834764831845f;  // 1/sqrt(128)
    float4 q4 = *(const float4*)&g_proj[(size_t)i * DPROJ + 4 * lx];
    float4 r4 = *(const float4*)&g_proj[(size_t)i * DPROJ + 192 + 4 * lx];
    q4.x *= scale; q4.y *= scale; q4.z *= scale; q4.w *= scale;
    r4.x *= scale; r4.y *= scale; r4.z *= scale; r4.w *= scale;

    const float* Drow = D + (size_t)i * NROWS * DR;

    // ---- prefetch tile 0 (K+V: 32 keys x 256B each = 16 KB) ----
    {
#pragma unroll
        for (int r = 0; r < 2; r++) {
            const int c   = tid + r * 256;      // 0..511
            const int key = c >> 4;
            const int off = c & 15;             // 16B units
            const float* src = &g_proj[(size_t)(jq + key) * DPROJ + off * 4];
            cp16(smem_u32(&Ks[key * DK + off * 4]), src + DK);
            cp16(smem_u32(&Vs[key * DV + off * 4]), src + 2 * DK);
        }
        asm volatile("cp.async.commit_group;" ::: "memory");
    }

    float  m = -CUDART_INF_F;
    float  l = 0.f;
    float4 acc = make_float4(0.f, 0.f, 0.f, 0.f);

#pragma unroll 1
    for (int t = 0; t < NT; t++) {
        const int st = t & 1;
        if (t + 1 < NT) {
            const int jt = jq + (t + 1) * TILE_KEYS;
            const int sn = (t + 1) & 1;
#pragma unroll
            for (int r = 0; r < 2; r++) {
                const int c   = tid + r * 256;
                const int key = c >> 4;
                const int off = c & 15;
                const float* src = &g_proj[(size_t)(jt + key) * DPROJ + off * 4];
                cp16(smem_u32(&Ks[sn * TILE_KEYS * DK + key * DK + off * 4]), src + DK);
                cp16(smem_u32(&Vs[sn * TILE_KEYS * DV + key * DV + off * 4]), src + 2 * DK);
            }
            asm volatile("cp.async.commit_group;" ::: "memory");
            asm volatile("cp.async.wait_group 1;" ::: "memory");
        } else {
            asm volatile("cp.async.wait_group 0;" ::: "memory");
        }
        __syncthreads();

        const float* Kt = Ks + st * TILE_KEYS * DK;
        const float* Vt = Vs + st * TILE_KEYS * DV;
        const int jt0 = jq + t * TILE_KEYS;

#pragma unroll
        for (int s = 0; s < 4; s++) {
            // ---- 8 keys per batch: 4 back-to-back 2KB-contiguous D loads ----
            float4 d4[4];
            float  sc[4];
#pragma unroll
            for (int u = 0; u < 4; u++) {
                const int kk = s * 8 + 2 * u + h;
                d4[u] = ldg_stream(&Drow[(size_t)(jt0 + kk) * DR + 4 * lx], pol);
            }
#pragma unroll
            for (int u = 0; u < 4; u++) {
                const int kk = s * 8 + 2 * u + h;
                const float4 k4 = *(const float4*)&Kt[kk * DK + 4 * lx];
                float t0 = d4[u].x * r4.x;
                t0 = fmaf(d4[u].y, r4.y, t0);
                t0 = fmaf(d4[u].z, r4.z, t0);
                t0 = fmaf(d4[u].w, r4.w, t0);
                t0 = fmaf(k4.x, q4.x, t0);
                t0 = fmaf(k4.y, q4.y, t0);
                t0 = fmaf(k4.z, q4.z, t0);
                t0 = fmaf(k4.w, q4.w, t0);
                sc[u] = t0;
            }
#pragma unroll
            for (int o = 1; o < 16; o <<= 1) {
#pragma unroll
                for (int u = 0; u < 4; u++)
                    sc[u] += __shfl_xor_sync(0xffffffffu, sc[u], o);
            }
            const float mnew = fmaxf(fmaxf(fmaxf(sc[0], sc[1]), fmaxf(sc[2], sc[3])), m);
            const float c = __expf(m - mnew);
            float w[4];
#pragma unroll
            for (int u = 0; u < 4; u++) w[u] = __expf(sc[u] - mnew);
            l = fmaf(l, c, (w[0] + w[1]) + (w[2] + w[3]));
            float ax = acc.x * c, ay = acc.y * c, az = acc.z * c, aw = acc.w * c;
#pragma unroll
            for (int u = 0; u < 4; u++) {
                const int kk = s * 8 + 2 * u + h;
                const float4 v4 = *(const float4*)&Vt[kk * DV + 4 * lx];
                ax = fmaf(w[u], v4.x, ax);
                ay = fmaf(w[u], v4.y, ay);
                az = fmaf(w[u], v4.z, az);
                aw = fmaf(w[u], v4.w, aw);
            }
            acc.x = ax; acc.y = ay; acc.z = az; acc.w = aw;
            m = mnew;
        }
        __syncthreads();   // tile consumed
    }

    // ---- combine the 2 group-partials per row -> per-split scratch ----
    if (lx == 0) { cm[warp * 2 + h] = m; cl[warp * 2 + h] = l; }
    *(float4*)&ca[(warp * 2 + h) * DV + 4 * lx] = acc;
    __syncthreads();

    {
        const int row = tid >> 5;           // 0..7
        const int dd  = (tid & 31) * 2;     // 2 dims per thread
        const int ig  = blockIdx.x * G_ROWS + row;
        const float m0 = cm[row * 2 + 0], m1 = cm[row * 2 + 1];
        const float M  = fmaxf(m0, m1);
        const float e0 = __expf(m0 - M);
        const float e1 = __expf(m1 - M);
        const float L  = e0 * cl[row * 2 + 0] + e1 * cl[row * 2 + 1];
        const float o0 = e0 * ca[(row * 2 + 0) * DV + dd + 0]
                       + e1 * ca[(row * 2 + 1) * DV + dd + 0];
        const float o1 = e0 * ca[(row * 2 + 0) * DV + dd + 1]
                       + e1 * ca[(row * 2 + 1) * DV + dd + 1];
        g_pa[q][ig][dd + 0] = o0;
        g_pa[q][ig][dd + 1] = o1;
        if (dd == 0) { g_ml[q][ig][0] = M; g_ml[q][ig][1] = L; }
    }
}

// ---------------------------------------------------------------------------
// Kernel 3: combine the four key-quarter partials per row.
// ---------------------------------------------------------------------------
__global__ __launch_bounds__(256) void combine_kernel(float* __restrict__ out)
{
    const int idx = blockIdx.x * 256 + threadIdx.x;   // 0 .. 2048*64-1
    const int i = idx >> 6;
    const int d = idx & 63;
    float M = g_ml[0][i][0];
#pragma unroll
    for (int p = 1; p < SPLITS; p++) M = fmaxf(M, g_ml[p][i][0]);
    float L = 0.f, o = 0.f;
#pragma unroll
    for (int p = 0; p < SPLITS; p++) {
        const float e = __expf(g_ml[p][i][0] - M);
        L = fmaf(g_ml[p][i][1], e, L);
        o = fmaf(g_pa[p][i][d], e, o);
    }
    out[idx] = o / L;
}

// ---------------------------------------------------------------------------
extern "C" void kernel_launch(void* const* d_in, const int* in_sizes, int n_in,
                              void* d_out, int out_size)
{
    const float* H = (const float*)d_in[0];   // (2048, 256)
    const float* D = (const float*)d_in[1];   // (2048, 2048, 64)
    const float* W = (const float*)d_in[2];   // (256, 256)
    float* out = (float*)d_out;               // (2048, 64)

    static bool attr_set = false;
    if (!attr_set) {
        cudaFuncSetAttribute(attn_partial_kernel,
                             cudaFuncAttributeMaxDynamicSharedMemorySize, SMEM_BYTES);
        cudaFuncSetAttribute(proj_gemm_kernel,
                             cudaFuncAttributeMaxDynamicSharedMemorySize, PROJ_SMEM_BYTES);
        attr_set = true;
    }

    dim3 g1(DPROJ / 64, NROWS / 64);          // (4, 32) = 128 blocks
    proj_gemm_kernel<<<g1, 128, PROJ_SMEM_BYTES>>>(H, W);
    attn_partial_kernel<<<dim3(NCTA_X, SPLITS), 256, SMEM_BYTES>>>(D);
    combine_kernel<<<(NROWS * DV) / 256, 256>>>(out);
}

// round 16
// speedup vs baseline: 1.3108x; 1.0243x over previous
#include <cuda_runtime.h>
#include <math_constants.h>
#include <cstdint>

#define NROWS 2048
#define DIN   256
#define DPROJ 256   // Q[0:64) K[64:128) V[128:192) R[192:256)
#define DK    64
#define DR    64
#define DV    64

#define G_ROWS     8            // rows per CTA (one warp per row)
#define TILE_KEYS  32           // keys per smem K/V tile
#define SPLITS     2            // key splits per row
#define KEYS_PER_CTA (NROWS / SPLITS)        // 1024
#define NT         (KEYS_PER_CTA / TILE_KEYS) // 32 tiles
#define NCTA_X     (NROWS / G_ROWS)          // 256
// dynamic smem: Ks[2][32][64] + Vs[2][32][64] + cm[16] + cl[16] + ca[8][2][64]
#define SMEM_FLOATS (2*TILE_KEYS*DK + 2*TILE_KEYS*DV + 16 + 16 + G_ROWS*2*DV)
#define SMEM_BYTES  (SMEM_FLOATS * 4)

// proj kernel smem: As[256][68] + Bs[256][68] (k-major, 64 rows used each)
#define PPAD 68
#define PROJ_SMEM_BYTES (2 * DIN * PPAD * 4)   // 139264

// Scratch
__device__ float g_proj[NROWS * DPROJ];          // projection (2 MB)
__device__ float g_ml[SPLITS][NROWS][2];         // per-split (M, L)
__device__ float g_pa[SPLITS][NROWS][DV];        // per-split unnormalized acc

__device__ __forceinline__ uint32_t smem_u32(const void* p) {
    return (uint32_t)__cvta_generic_to_shared(p);
}
__device__ __forceinline__ void cp16(uint32_t dst, const void* src) {
    asm volatile("cp.async.cg.shared.global [%0], [%1], 16;"
                 :: "r"(dst), "l"(src) : "memory");
}
__device__ __forceinline__ uint64_t mk_evict_first_policy() {
    uint64_t pol;
    asm("createpolicy.fractional.L2::evict_first.b64 %0, 1.0;" : "=l"(pol));
    return pol;
}
__device__ __forceinline__ float4 ldg_stream(const float* p, uint64_t pol) {
    float4 v;
    asm volatile("ld.global.nc.L2::cache_hint.v4.f32 {%0,%1,%2,%3}, [%4], %5;"
                 : "=f"(v.x), "=f"(v.y), "=f"(v.z), "=f"(v.w)
                 : "l"(p), "l"(pol));
    return v;
}
// ---- packed f32x2 helpers (sm_103a FFMA2 path) ----
__device__ __forceinline__ void fma2(unsigned long long& d,
                                     unsigned long long a,
                                     unsigned long long b) {
    asm("fma.rn.f32x2 %0, %1, %2, %0;" : "+l"(d) : "l"(a), "l"(b));
}
__device__ __forceinline__ unsigned long long bcast2(float x) {
    unsigned long long r;
    asm("mov.b64 %0, {%1, %1};" : "=l"(r) : "f"(x));
    return r;
}
__device__ __forceinline__ float lo2(unsigned long long v) {
    return __uint_as_float((unsigned)(v & 0xffffffffu));
}
__device__ __forceinline__ float hi2(unsigned long long v) {
    return __uint_as_float((unsigned)(v >> 32));
}

// ---------------------------------------------------------------------------
// Kernel 1: proj = H @ W^T.  64x64 tile, 256 threads, 4x4 outputs/thread via
// packed f32x2 FMA (2 row-pairs x 4 cols). Full-K k-major staging, one
// barrier. Grid (4,32)=128 CTAs, 8 warps/SM.
// ---------------------------------------------------------------------------
__global__ __launch_bounds__(256, 1) void proj_gemm_kernel(
    const float* __restrict__ H, const float* __restrict__ W)
{
    extern __shared__ float psm[];
    float* As = psm;                   // [DIN][PPAD] rows 0..63 used
    float* Bs = psm + DIN * PPAD;      // [DIN][PPAD] rows 0..63 used

    const int tid = threadIdx.x;
    const int bm  = blockIdx.y * 64;
    const int bn  = blockIdx.x * 64;

    // ---- stage H and W tiles (64 x 256 each), k-major ----
    {
        const int row = tid >> 2;           // 0..63
        const int c   = (tid & 3) * 4;      // k sub-offset
#pragma unroll
        for (int kc = 0; kc < DIN; kc += 16) {
            float4 a4 = *(const float4*)&H[(size_t)(bm + row) * DIN + kc + c];
            As[(kc + c + 0) * PPAD + row] = a4.x;
            As[(kc + c + 1) * PPAD + row] = a4.y;
            As[(kc + c + 2) * PPAD + row] = a4.z;
            As[(kc + c + 3) * PPAD + row] = a4.w;
            float4 b4 = *(const float4*)&W[(size_t)(bn + row) * DIN + kc + c];
            Bs[(kc + c + 0) * PPAD + row] = b4.x;
            Bs[(kc + c + 1) * PPAD + row] = b4.y;
            Bs[(kc + c + 2) * PPAD + row] = b4.z;
            Bs[(kc + c + 3) * PPAD + row] = b4.w;
        }
    }
    __syncthreads();   // the only barrier

    const int tx = tid & 15;        // 4 output cols
    const int ty = tid >> 4;        // 4 output rows (2 row-pairs)

    unsigned long long acc2[2][4];
#pragma unroll
    for (int a = 0; a < 2; a++)
#pragma unroll
        for (int b = 0; b < 4; b++) acc2[a][b] = 0ull;

#pragma unroll 4
    for (int k = 0; k < DIN; k++) {
        // 4 a-values = 2 packed row-pairs (one LDS.128, 16B-aligned: 272B row stride)
        const ulonglong2 ap = *(const ulonglong2*)&As[k * PPAD + ty * 4];
        const float4 bf = *(const float4*)&Bs[k * PPAD + tx * 4];
        const unsigned long long bp0 = bcast2(bf.x);
        const unsigned long long bp1 = bcast2(bf.y);
        const unsigned long long bp2 = bcast2(bf.z);
        const unsigned long long bp3 = bcast2(bf.w);

        fma2(acc2[0][0], ap.x, bp0); fma2(acc2[0][1], ap.x, bp1);
        fma2(acc2[0][2], ap.x, bp2); fma2(acc2[0][3], ap.x, bp3);
        fma2(acc2[1][0], ap.y, bp0); fma2(acc2[1][1], ap.y, bp1);
        fma2(acc2[1][2], ap.y, bp2); fma2(acc2[1][3], ap.y, bp3);
    }

#pragma unroll
    for (int rp = 0; rp < 2; rp++) {
        const int row = bm + ty * 4 + rp * 2;
        *(float4*)&g_proj[(size_t)row * DPROJ + bn + tx * 4] =
            make_float4(lo2(acc2[rp][0]), lo2(acc2[rp][1]),
                        lo2(acc2[rp][2]), lo2(acc2[rp][3]));
        *(float4*)&g_proj[(size_t)(row + 1) * DPROJ + bn + tx * 4] =
            make_float4(hi2(acc2[rp][0]), hi2(acc2[rp][1]),
                        hi2(acc2[rp][2]), hi2(acc2[rp][3]));
    }
}

// ---------------------------------------------------------------------------
// Kernel 2: partial fused attention (exact R10 inner loop), 2-way key split.
// Grid (256, 2): blockIdx.x -> 8-row group, blockIdx.y = key half.
// Warp w owns row w; 16-lane groups (h = lane>>4) own alternating keys,
// lane&15 owns 4 dims; K/V double-buffered smem tiles via cp.async;
// D streamed as 4 back-to-back float4 LDG (evict-first cache hint).
// ---------------------------------------------------------------------------
__global__ void __launch_bounds__(256, 4) attn_partial_kernel(
    const float* __restrict__ D)
{
    extern __shared__ float smem[];
    float* Ks = smem;                       // [2][TILE_KEYS][DK]
    float* Vs = Ks + 2 * TILE_KEYS * DK;    // [2][TILE_KEYS][DV]
    float* cm = Vs + 2 * TILE_KEYS * DV;    // [G_ROWS][2]
    float* cl = cm + 16;                    // [G_ROWS][2]
    float* ca = cl + 16;                    // [G_ROWS][2][DV]

    const int tid  = threadIdx.x;
    const int warp = tid >> 5;           // = row within CTA
    const int lane = tid & 31;
    const int h    = lane >> 4;          // group in warp
    const int lx   = lane & 15;          // lane in group -> dims 4*lx..+4
    const int q    = blockIdx.y;         // key half
    const int i    = blockIdx.x * G_ROWS + warp;
    const int jq   = q * KEYS_PER_CTA;

    const uint64_t pol = mk_evict_first_policy();

    const float scale = 0.08838834764831845f;  // 1/sqrt(128)
    float4 q4 = *(const float4*)&g_proj[(size_t)i * DPROJ + 4 * lx];
    float4 r4 = *(const float4*)&g_proj[(size_t)i * DPROJ + 192 + 4 * lx];
    q4.x *= scale; q4.y *= scale; q4.z *= scale; q4.w *= scale;
    r4.x *= scale; r4.y *= scale; r4.z *= scale; r4.w *= scale;

    const float* Drow = D + (size_t)i * NROWS * DR;

    // ---- prefetch tile 0 (K+V: 32 keys x 256B each = 16 KB) ----
    {
#pragma unroll
        for (int r = 0; r < 2; r++) {
            const int c   = tid + r * 256;      // 0..511
            const int key = c >> 4;
            const int off = c & 15;             // 16B units
            const float* src = &g_proj[(size_t)(jq + key) * DPROJ + off * 4];
            cp16(smem_u32(&Ks[key * DK + off * 4]), src + DK);
            cp16(smem_u32(&Vs[key * DV + off * 4]), src + 2 * DK);
        }
        asm volatile("cp.async.commit_group;" ::: "memory");
    }

    float  m = -CUDART_INF_F;
    float  l = 0.f;
    float4 acc = make_float4(0.f, 0.f, 0.f, 0.f);

#pragma unroll 1
    for (int t = 0; t < NT; t++) {
        const int st = t & 1;
        if (t + 1 < NT) {
            const int jt = jq + (t + 1) * TILE_KEYS;
            const int sn = (t + 1) & 1;
#pragma unroll
            for (int r = 0; r < 2; r++) {
                const int c   = tid + r * 256;
                const int key = c >> 4;
                const int off = c & 15;
                const float* src = &g_proj[(size_t)(jt + key) * DPROJ + off * 4];
                cp16(smem_u32(&Ks[sn * TILE_KEYS * DK + key * DK + off * 4]), src + DK);
                cp16(smem_u32(&Vs[sn * TILE_KEYS * DV + key * DV + off * 4]), src + 2 * DK);
            }
            asm volatile("cp.async.commit_group;" ::: "memory");
            asm volatile("cp.async.wait_group 1;" ::: "memory");
        } else {
            asm volatile("cp.async.wait_group 0;" ::: "memory");
        }
        __syncthreads();

        const float* Kt = Ks + st * TILE_KEYS * DK;
        const float* Vt = Vs + st * TILE_KEYS * DV;
        const int jt0 = jq + t * TILE_KEYS;

#pragma unroll
        for (int s = 0; s < 4; s++) {
            // ---- 8 keys per batch: 4 back-to-back 2KB-contiguous D loads ----
            float4 d4[4];
            float  sc[4];
#pragma unroll
            for (int u = 0; u < 4; u++) {
                const int kk = s * 8 + 2 * u + h;
                d4[u] = ldg_stream(&Drow[(size_t)(jt0 + kk) * DR + 4 * lx], pol);
            }
#pragma unroll
            for (int u = 0; u < 4; u++) {
                const int kk = s * 8 + 2 * u + h;
                const float4 k4 = *(const float4*)&Kt[kk * DK + 4 * lx];
                float t0 = d4[u].x * r4.x;
                t0 = fmaf(d4[u].y, r4.y, t0);
                t0 = fmaf(d4[u].z, r4.z, t0);
                t0 = fmaf(d4[u].w, r4.w, t0);
                t0 = fmaf(k4.x, q4.x, t0);
                t0 = fmaf(k4.y, q4.y, t0);
                t0 = fmaf(k4.z, q4.z, t0);
                t0 = fmaf(k4.w, q4.w, t0);
                sc[u] = t0;
            }
#pragma unroll
            for (int o = 1; o < 16; o <<= 1) {
#pragma unroll
                for (int u = 0; u < 4; u++)
                    sc[u] += __shfl_xor_sync(0xffffffffu, sc[u], o);
            }
            const float mnew = fmaxf(fmaxf(fmaxf(sc[0], sc[1]), fmaxf(sc[2], sc[3])), m);
            const float c = __expf(m - mnew);
            float w[4];
#pragma unroll
            for (int u = 0; u < 4; u++) w[u] = __expf(sc[u] - mnew);
            l = fmaf(l, c, (w[0] + w[1]) + (w[2] + w[3]));
            float ax = acc.x * c, ay = acc.y * c, az = acc.z * c, aw = acc.w * c;
#pragma unroll
            for (int u = 0; u < 4; u++) {
                const int kk = s * 8 + 2 * u + h;
                const float4 v4 = *(const float4*)&Vt[kk * DV + 4 * lx];
                ax = fmaf(w[u], v4.x, ax);
                ay = fmaf(w[u], v4.y, ay);
                az = fmaf(w[u], v4.z, az);
                aw = fmaf(w[u], v4.w, aw);
            }
            acc.x = ax; acc.y = ay; acc.z = az; acc.w = aw;
            m = mnew;
        }
        __syncthreads();   // tile consumed
    }

    // ---- combine the 2 group-partials per row -> per-split scratch ----
    if (lx == 0) { cm[warp * 2 + h] = m; cl[warp * 2 + h] = l; }
    *(float4*)&ca[(warp * 2 + h) * DV + 4 * lx] = acc;
    __syncthreads();

    {
        const int row = tid >> 5;           // 0..7
        const int dd  = (tid & 31) * 2;     // 2 dims per thread
        const int ig  = blockIdx.x * G_ROWS + row;
        const float m0 = cm[row * 2 + 0], m1 = cm[row * 2 + 1];
        const float M  = fmaxf(m0, m1);
        const float e0 = __expf(m0 - M);
        const float e1 = __expf(m1 - M);
        const float L  = e0 * cl[row * 2 + 0] + e1 * cl[row * 2 + 1];
        const float o0 = e0 * ca[(row * 2 + 0) * DV + dd + 0]
                       + e1 * ca[(row * 2 + 1) * DV + dd + 0];
        const float o1 = e0 * ca[(row * 2 + 0) * DV + dd + 1]
                       + e1 * ca[(row * 2 + 1) * DV + dd + 1];
        g_pa[q][ig][dd + 0] = o0;
        g_pa[q][ig][dd + 1] = o1;
        if (dd == 0) { g_ml[q][ig][0] = M; g_ml[q][ig][1] = L; }
    }
}

// ---------------------------------------------------------------------------
// Kernel 3: combine the two key-half partials per row.
// ---------------------------------------------------------------------------
__global__ __launch_bounds__(256) void combine_kernel(float* __restrict__ out)
{
    const int idx = blockIdx.x * 256 + threadIdx.x;   // 0 .. 2048*64-1
    const int i = idx >> 6;
    const int d = idx & 63;
    const float m0 = g_ml[0][i][0], l0 = g_ml[0][i][1];
    const float m1 = g_ml[1][i][0], l1 = g_ml[1][i][1];
    const float M  = fmaxf(m0, m1);
    const float e0 = __expf(m0 - M);
    const float e1 = __expf(m1 - M);
    const float L  = e0 * l0 + e1 * l1;
    out[idx] = (e0 * g_pa[0][i][d] + e1 * g_pa[1][i][d]) / L;
}

// ---------------------------------------------------------------------------
extern "C" void kernel_launch(void* const* d_in, const int* in_sizes, int n_in,
                              void* d_out, int out_size)
{
    const float* H = (const float*)d_in[0];   // (2048, 256)
    const float* D = (const float*)d_in[1];   // (2048, 2048, 64)
    const float* W = (const float*)d_in[2];   // (256, 256)
    float* out = (float*)d_out;               // (2048, 64)

    static bool attr_set = false;
    if (!attr_set) {
        cudaFuncSetAttribute(attn_partial_kernel,
                             cudaFuncAttributeMaxDynamicSharedMemorySize, SMEM_BYTES);
        cudaFuncSetAttribute(proj_gemm_kernel,
                             cudaFuncAttributeMaxDynamicSharedMemorySize, PROJ_SMEM_BYTES);
        attr_set = true;
    }

    dim3 g1(DPROJ / 64, NROWS / 64);          // (4, 32) = 128 blocks
    proj_gemm_kernel<<<g1, 256, PROJ_SMEM_BYTES>>>(H, W);
    attn_partial_kernel<<<dim3(NCTA_X, SPLITS), 256, SMEM_BYTES>>>(D);
    combine_kernel<<<(NROWS * DV) / 256, 256>>>(out);
}